// round 9
// baseline (speedup 1.0000x reference)
#include <cuda_runtime.h>
#include <cuda_bf16.h>
#include <cstdint>

// ============================================================================
// SimplifiedTopologyExtractor — algebraic reduction:
//   out = ReLU(LayerNorm(emb[:, :, :256] @ W_enc + b_enc))
// (pooled == embeddings exactly; proj/cdist/topk is dead code.)
//
// fp32 GEMM via bf16 hi/lo split on mma.sync m16n8k16:
//   a*b ≈ ah*bh + ah*bl + al*bh   (err ~2^-18 rel).
// Round 9: decoupled-warp mainloop. A converted to smem ONCE up front
// (64KB, all 16 chunks); B via one cp.async.bulk per 32KB chunk into a
// 4-stage ring guarded by full(expect_tx)/empty(count-16) mbarriers.
// NO __syncthreads in the mainloop — warps free-run, so LDSM crossbar
// phases of some warps overlap MMA phases of others.
// ============================================================================

#define THREADS 512
#define MTILE 64
#define KD 256
#define KCH 16
#define NCHUNK (KD / KCH)
#define STAGES 4
#define B_CHUNK 32768

// smem layout (bytes)
#define OFF_A     0                      // 16 chunks x 4096 (hi 2KB + lo 2KB)
#define OFF_B     65536                  // 4 stages x 32768
#define OFF_FULL  (OFF_B + STAGES * B_CHUNK)    // 196608
#define OFF_EMPTY (OFF_FULL + 32)
#define OFF_PS    (OFF_EMPTY + 32)
#define OFF_PQ    (OFF_PS + 1024)
#define OFF_MZ    (OFF_PQ + 1024)
#define SMEM_TOTAL (OFF_MZ + 512)        // 199232

// prepped B (bf16 hi/lo), chunk-shaped + XOR-unit swizzle (as R8):
//   [chunk 16][part 2][kr 16][unit 64], unit' = unit ^ (kr&7)
__device__ __align__(128) unsigned char g_Bpre[16 * B_CHUNK];   // 512 KB

__device__ __forceinline__ uint32_t smem_u32(const void* p) {
    uint32_t a;
    asm("{ .reg .u64 t; cvta.to.shared.u64 t, %1; cvt.u32.u64 %0, t; }"
        : "=r"(a) : "l"(p));
    return a;
}

__device__ __forceinline__ void ldsm4(uint32_t* r, uint32_t addr) {
    asm volatile("ldmatrix.sync.aligned.m8n8.x4.shared.b16 {%0,%1,%2,%3}, [%4];"
                 : "=r"(r[0]), "=r"(r[1]), "=r"(r[2]), "=r"(r[3]) : "r"(addr));
}
__device__ __forceinline__ void ldsm4t(uint32_t* r, uint32_t addr) {
    asm volatile("ldmatrix.sync.aligned.m8n8.x4.trans.shared.b16 {%0,%1,%2,%3}, [%4];"
                 : "=r"(r[0]), "=r"(r[1]), "=r"(r[2]), "=r"(r[3]) : "r"(addr));
}

__device__ __forceinline__ void mma16816(float* d, const uint32_t* a,
                                         uint32_t b0, uint32_t b1) {
    asm volatile(
        "mma.sync.aligned.m16n8k16.row.col.f32.bf16.bf16.f32 "
        "{%0,%1,%2,%3}, {%4,%5,%6,%7}, {%8,%9}, {%0,%1,%2,%3};"
        : "+f"(d[0]), "+f"(d[1]), "+f"(d[2]), "+f"(d[3])
        : "r"(a[0]), "r"(a[1]), "r"(a[2]), "r"(a[3]), "r"(b0), "r"(b1));
}

#define MBAR_INIT(addr, cnt) \
    asm volatile("mbarrier.init.shared.b64 [%0], %1;" :: "r"(addr), "r"(cnt) : "memory")

#define MBAR_ARRIVE(addr) \
    asm volatile("mbarrier.arrive.shared.b64 _, [%0];" :: "r"(addr) : "memory")

#define MBAR_EXPECT_TX(addr, bytes) \
    asm volatile("mbarrier.arrive.expect_tx.shared.b64 _, [%0], %1;" \
                 :: "r"(addr), "r"((uint32_t)(bytes)) : "memory")

#define MBAR_WAIT(addr, par) do {                                              \
    uint32_t _m = (addr), _p = (uint32_t)(par), _done;                         \
    asm volatile("{\n\t.reg .pred p;\n\t"                                      \
        "mbarrier.try_wait.parity.acquire.cta.shared::cta.b64 p, [%1], %2;\n\t"\
        "selp.b32 %0, 1, 0, p;\n\t}" : "=r"(_done) : "r"(_m), "r"(_p) : "memory"); \
    if (!_done) {                                                              \
        asm volatile("{\n\t.reg .pred P1;\n\t"                                 \
            "W%=:\n\t"                                                         \
            "mbarrier.try_wait.parity.acquire.cta.shared::cta.b64 P1, [%0], %1, 0x989680;\n\t" \
            "@P1 bra.uni D%=;\n\t"                                             \
            "bra.uni W%=;\n\t"                                                 \
            "D%=:\n\t}" :: "r"(_m), "r"(_p) : "memory");                       \
    }                                                                          \
} while (0)

__device__ __forceinline__ void bulk_copy(uint32_t dst, const void* src,
                                          uint32_t bytes, uint32_t mbar) {
    asm volatile(
        "cp.async.bulk.shared::cluster.global.mbarrier::complete_tx::bytes "
        "[%0], [%1], %2, [%3];"
        :: "r"(dst), "l"(src), "r"(bytes), "r"(mbar) : "memory");
}

__device__ __forceinline__ void split_f4(float4 v, uint32_t& h01, uint32_t& h23,
                                         uint32_t& l01, uint32_t& l23) {
    float f[4] = {v.x, v.y, v.z, v.w};
    unsigned short hs[4], ls[4];
#pragma unroll
    for (int i = 0; i < 4; i++) {
        __nv_bfloat16 h = __float2bfloat16(f[i]);
        float rem = f[i] - __bfloat162float(h);
        __nv_bfloat16 l = __float2bfloat16(rem);
        hs[i] = __bfloat16_as_ushort(h);
        ls[i] = __bfloat16_as_ushort(l);
    }
    h01 = (uint32_t)hs[0] | ((uint32_t)hs[1] << 16);
    h23 = (uint32_t)hs[2] | ((uint32_t)hs[3] << 16);
    l01 = (uint32_t)ls[0] | ((uint32_t)ls[1] << 16);
    l23 = (uint32_t)ls[2] | ((uint32_t)ls[3] << 16);
}

// ---- prep B: W_enc[256,512] -> hi/lo bf16, chunk-tiled + XOR swizzle ----
__global__ void prep_b_kernel(const float* __restrict__ W) {
    int t = blockIdx.x * 256 + threadIdx.x;   // 256 k x 128 nq
    int k  = t >> 7;
    int nq = t & 127;
    float4 v = *(const float4*)(W + (size_t)k * 512 + nq * 4);
    uint32_t h01, h23, l01, l23;
    split_f4(v, h01, h23, l01, l23);
    int c = k >> 4, kr = k & 15;
    int unit = nq >> 1;
    int sw   = unit ^ (kr & 7);
    size_t base = (size_t)c * B_CHUNK + (size_t)kr * 1024
                + (size_t)sw * 16 + (nq & 1) * 8;
    *(uint2*)(g_Bpre + base)         = make_uint2(h01, h23);
    *(uint2*)(g_Bpre + base + 16384) = make_uint2(l01, l23);
}

// ---- GEMM + fused bias/LayerNorm/ReLU ----
__global__ void __launch_bounds__(THREADS, 1)
gemm_ln_kernel(const float* __restrict__ emb,
               const float* __restrict__ bias,
               const float* __restrict__ gamma,
               const float* __restrict__ beta,
               float* __restrict__ out)
{
    extern __shared__ __align__(1024) unsigned char smem[];
    const uint32_t sb = smem_u32(smem);
    const int tid = threadIdx.x;
    const int wid = tid >> 5;
    const int lane = tid & 31;
    const int mw = wid >> 2;       // 4 m-warps
    const int nw = wid & 3;        // 4 n-warps
    const int m0 = blockIdx.x * MTILE;

    float acc[16][4];
#pragma unroll
    for (int nt = 0; nt < 16; nt++)
#pragma unroll
        for (int e = 0; e < 4; e++) acc[nt][e] = 0.0f;

    // mbarriers: full[s] count=1 (tx-based), empty[s] count=16 (1/warp)
    if (tid == 0) {
#pragma unroll
        for (int s = 0; s < STAGES; s++) {
            MBAR_INIT(sb + OFF_FULL + s * 8, 1);
            MBAR_INIT(sb + OFF_EMPTY + s * 8, 16);
        }
    }
    __syncthreads();

    // kick off B chunks 0..2 (stage 3 filled from inside the loop at c=0)
    if (tid == 0) {
#pragma unroll
        for (int cc = 0; cc < 3; cc++) {
            MBAR_EXPECT_TX(sb + OFF_FULL + cc * 8, B_CHUNK);
            bulk_copy(sb + OFF_B + (uint32_t)cc * B_CHUNK,
                      g_Bpre + (size_t)cc * B_CHUNK, B_CHUNK,
                      sb + OFF_FULL + cc * 8);
        }
    }

    // ---- A: convert all 16 chunks to smem once ----
    // layout: [chunk][part 2048][row*32 + ((unit ^ ((row>>2)&1))<<4)]
    {
        const int arow = tid >> 3;
        const int k32 = (tid & 7) * 32;
        const float* ap = emb + (size_t)(m0 + arow) * 512 + k32;
        const uint32_t rsw = (uint32_t)((arow >> 2) & 1);
#pragma unroll
        for (int uu = 0; uu < 4; uu++) {
            float4 v0 = *(const float4*)(ap + uu * 8);
            float4 v1 = *(const float4*)(ap + uu * 8 + 4);
            uint32_t h0, h1, h2, h3, l0, l1, l2, l3;
            split_f4(v0, h0, h1, l0, l1);
            split_f4(v1, h2, h3, l2, l3);
            const int kglob = k32 + uu * 8;
            const int ch = kglob >> 4;
            const uint32_t unitIdx = (uint32_t)((kglob >> 3) & 1);
            const uint32_t base = (uint32_t)ch * 4096 + (uint32_t)arow * 32
                                + ((unitIdx ^ rsw) << 4);
            *(uint4*)(smem + OFF_A + base)        = make_uint4(h0, h1, h2, h3);
            *(uint4*)(smem + OFF_A + base + 2048) = make_uint4(l0, l1, l2, l3);
        }
    }
    __syncthreads();   // A visible to all warps; mainloop is sync-free

    // lane addressing
    const uint32_t lrow = lane & 15, lchk = lane >> 4;
    const uint32_t arow_l = (uint32_t)mw * 16 + lrow;
    const uint32_t aBase = arow_l * 32
                         + ((lchk ^ ((arow_l >> 2) & 1)) << 4);  // + part*2048
    const uint32_t bRow = lrow * 1024;
    const uint32_t swz  = lrow & 7;
    const uint32_t uBase = (uint32_t)nw * 16 + lchk;

#pragma unroll 1
    for (int c = 0; c < NCHUNK; ++c) {
        const int s = c & 3;
        MBAR_WAIT(sb + OFF_FULL + s * 8, (c >> 2) & 1);   // B(c) landed

        const uint32_t aCh = sb + OFF_A + (uint32_t)c * 4096 + aBase;
        uint32_t Ah[4], Al[4];
        ldsm4(Ah, aCh);
        ldsm4(Al, aCh + 2048);
        const uint32_t bH = sb + OFF_B + (uint32_t)s * B_CHUNK + bRow;
#pragma unroll
        for (int j = 0; j < 8; j++) {
            const uint32_t u = uBase + (uint32_t)j * 2;
            const uint32_t addrH = bH + ((u ^ swz) << 4);
            uint32_t Bh[4], Bl[4];
            ldsm4t(Bh, addrH);
            ldsm4t(Bl, addrH + 16384);
#pragma unroll
            for (int nn = 0; nn < 2; nn++) {
                float* d = acc[j * 2 + nn];
                mma16816(d, Ah, Bh[nn * 2], Bh[nn * 2 + 1]);
                mma16816(d, Ah, Bl[nn * 2], Bl[nn * 2 + 1]);
                mma16816(d, Al, Bh[nn * 2], Bh[nn * 2 + 1]);
            }
        }
        // this warp is done reading stage s (MMAs above depend on the LDSMs)
        if (lane == 0) MBAR_ARRIVE(sb + OFF_EMPTY + s * 8);

        // producer: refill stage (c+3)&3 with chunk c+3
        if (tid == 0 && c + 3 < NCHUNK) {
            const int cN = c + 3, sN = cN & 3;
            if (c >= 1)
                MBAR_WAIT(sb + OFF_EMPTY + sN * 8, ((c - 1) >> 2) & 1);
            MBAR_EXPECT_TX(sb + OFF_FULL + sN * 8, B_CHUNK);
            bulk_copy(sb + OFF_B + (uint32_t)sN * B_CHUNK,
                      g_Bpre + (size_t)cN * B_CHUNK, B_CHUNK,
                      sb + OFF_FULL + sN * 8);
        }
    }

    // ======== fused epilogue: +bias, LayerNorm(512), *gamma+beta, ReLU ========
    const int g = lane >> 2, t4 = lane & 3;
    float* ps = (float*)(smem + OFF_PS);      // [64 rows][4 nw]
    float* pq = (float*)(smem + OFF_PQ);
    float2* mz = (float2*)(smem + OFF_MZ);    // [64] {mu, rstd}

    float sA[2] = {0.f, 0.f}, qA[2] = {0.f, 0.f};
#pragma unroll
    for (int nt = 0; nt < 16; nt++) {
        const int col = nw * 128 + nt * 8 + t4 * 2;
        const float2 bv = *(const float2*)(bias + col);
        acc[nt][0] += bv.x; acc[nt][1] += bv.y;
        acc[nt][2] += bv.x; acc[nt][3] += bv.y;
        sA[0] += acc[nt][0] + acc[nt][1];
        qA[0] += acc[nt][0] * acc[nt][0] + acc[nt][1] * acc[nt][1];
        sA[1] += acc[nt][2] + acc[nt][3];
        qA[1] += acc[nt][2] * acc[nt][2] + acc[nt][3] * acc[nt][3];
    }
#pragma unroll
    for (int h = 0; h < 2; h++) {
        sA[h] += __shfl_xor_sync(0xffffffffu, sA[h], 1);
        qA[h] += __shfl_xor_sync(0xffffffffu, qA[h], 1);
        sA[h] += __shfl_xor_sync(0xffffffffu, sA[h], 2);
        qA[h] += __shfl_xor_sync(0xffffffffu, qA[h], 2);
    }
    if (t4 == 0) {
#pragma unroll
        for (int h = 0; h < 2; h++) {
            const int row = mw * 16 + h * 8 + g;
            ps[row * 4 + nw] = sA[h];
            pq[row * 4 + nw] = qA[h];
        }
    }
    __syncthreads();
    if (tid < 64) {
        float ss = ps[tid * 4 + 0] + ps[tid * 4 + 1]
                 + ps[tid * 4 + 2] + ps[tid * 4 + 3];
        float qq = pq[tid * 4 + 0] + pq[tid * 4 + 1]
                 + pq[tid * 4 + 2] + pq[tid * 4 + 3];
        const float mu  = ss * (1.0f / 512.0f);
        const float var = qq * (1.0f / 512.0f) - mu * mu;
        mz[tid] = make_float2(mu, rsqrtf(var + 1e-5f));
    }
    __syncthreads();

#pragma unroll
    for (int h = 0; h < 2; h++) {
        const int row = mw * 16 + h * 8 + g;
        const float2 m = mz[row];
#pragma unroll
        for (int nt = 0; nt < 16; nt++) {
            const int col = nw * 128 + nt * 8 + t4 * 2;
            const float2 gv = *(const float2*)(gamma + col);
            const float2 tv = *(const float2*)(beta + col);
            const float v0 = acc[nt][h * 2 + 0];
            const float v1 = acc[nt][h * 2 + 1];
            const float o0 = fmaxf((v0 - m.x) * m.y * gv.x + tv.x, 0.0f);
            const float o1 = fmaxf((v1 - m.x) * m.y * gv.y + tv.y, 0.0f);
            *(float2*)(out + (size_t)(m0 + row) * 512 + col) = make_float2(o0, o1);
        }
    }
}

extern "C" void kernel_launch(void* const* d_in, const int* in_sizes, int n_in,
                              void* d_out, int out_size)
{
    // metadata order: embeddings, W_proj, b_proj, W_enc, b_enc, ln_gamma, ln_beta
    const float* emb   = (const float*)d_in[0];
    const float* W_enc = (const float*)d_in[3];
    const float* b_enc = (const float*)d_in[4];
    const float* gam   = (const float*)d_in[5];
    const float* bet   = (const float*)d_in[6];
    float* out = (float*)d_out;

    prep_b_kernel<<<128, 256>>>(W_enc);

    cudaFuncSetAttribute(gemm_ln_kernel,
                         cudaFuncAttributeMaxDynamicSharedMemorySize, SMEM_TOTAL);
    gemm_ln_kernel<<<16384 / MTILE, THREADS, SMEM_TOTAL>>>(emb, b_enc, gam, bet, out);
}